// round 11
// baseline (speedup 1.0000x reference)
#include <cuda_runtime.h>
#include <cuda_bf16.h>
#include <cstdint>

typedef unsigned long long ull;

// ---------------- device-global scratch (no runtime alloc allowed) -------------
// Weight tables, kk-major: idx = kk*512 + g*128 + n -> float2 {w(2kk), w(2kk+1)}
// (256KB each; conflict-free LDS.64 per (kk,g) across lanes n)
__device__ float2 g_wsE[64 * 4 * 128];
__device__ float2 g_wsD[64 * 4 * 128];
__device__ ull    g_abE[128 * 4 * 3];      // per (n,gate): {bias,bias},{a0,a0},{a1,a1}
__device__ ull    g_abD[128 * 4 * 3];
__device__ float  g_Wm1T[128 * 256];       // [k][mc]
__device__ float  g_Wm2T[256 * 112];       // [k][mc]

// ---------------- f32x2 + async helpers ----------------------------------------
__device__ __forceinline__ ull f2fma(ull a, ull b, ull c) {
    ull d;
    asm("fma.rn.f32x2 %0, %1, %2, %3;" : "=l"(d) : "l"(a), "l"(b), "l"(c));
    return d;
}
__device__ __forceinline__ ull pk(float lo, float hi) {
    ull r;
    asm("mov.b64 %0, {%1, %2};" : "=l"(r) : "f"(lo), "f"(hi));
    return r;
}
__device__ __forceinline__ float2 unpk(ull v) {
    float2 r;
    asm("mov.b64 {%0, %1}, %2;" : "=f"(r.x), "=f"(r.y) : "l"(v));
    return r;
}
// HW tanh (MUFU.TANH). sigmoid(x) = 0.5*tanh(x/2) + 0.5
__device__ __forceinline__ float tanha_(float x) {
    float r;
    asm("tanh.approx.f32 %0, %1;" : "=f"(r) : "f"(x));
    return r;
}
__device__ __forceinline__ float sigma_(float x) {
    return fmaf(0.5f, tanha_(0.5f * x), 0.5f);
}
__device__ __forceinline__ void mbar_expect_bulk(uint32_t mb, uint32_t dst,
                                                 const void* src, uint32_t bytes) {
    asm volatile("mbarrier.arrive.expect_tx.shared.b64 _, [%0], %1;"
                 :: "r"(mb), "r"(bytes) : "memory");
    asm volatile("cp.async.bulk.shared::cluster.global.mbarrier::complete_tx::bytes "
                 "[%0], [%1], %2, [%3];"
                 :: "r"(dst), "l"(src), "r"(bytes), "r"(mb) : "memory");
}
__device__ __forceinline__ void mbar_wait(uint32_t mb, int parity) {
    asm volatile(
        "{\n\t.reg .pred P1;\n\t"
        "WL_%=:\n\t"
        "mbarrier.try_wait.parity.shared.b64 P1, [%0], %1;\n\t"
        "@!P1 bra WL_%=;\n\t}"
        :: "r"(mb), "r"(parity) : "memory");
}

// ---------------- fused precompute kernel --------------------------------------
__global__ void k_prep(const float* __restrict__ Wih_e, const float* __restrict__ We,
                       const float* __restrict__ be,   const float* __restrict__ b_e,
                       const float* __restrict__ Wih_d, const float* __restrict__ Wd,
                       const float* __restrict__ bd,   const float* __restrict__ b_d,
                       const float* __restrict__ Whh_e, const float* __restrict__ Whh_d,
                       const float* __restrict__ Wm1,  const float* __restrict__ Wm2,
                       int E)
{
    int idx0 = blockIdx.x * blockDim.x + threadIdx.x;
    int stride = gridDim.x * blockDim.x;

    // fold A = Wih @ Win (512x2), bias = Wih @ bin + bgate  (encoder + decoder)
    for (int i = idx0; i < 1024; i += stride) {
        int which = i >> 9;          // 0 = enc, 1 = dec
        int gn = i & 511;
        const float* Wih = which ? Wih_d : Wih_e;
        const float* Win = which ? Wd : We;
        const float* bin = which ? bd : be;
        const float* bg  = which ? b_d : b_e;
        ull* ab_out = which ? g_abD : g_abE;
        float a0 = 0.f, a1 = 0.f, bb = 0.f;
        for (int e = 0; e < E; e++) {
            float w = Wih[gn * E + e];
            a0 += w * Win[e * 2 + 0];
            a1 += w * Win[e * 2 + 1];
            bb += w * bin[e];
        }
        bb += bg[gn];
        int n = gn & 127, g = gn >> 7;
        ab_out[(n * 4 + g) * 3 + 0] = pk(bb, bb);
        ab_out[(n * 4 + g) * 3 + 1] = pk(a0, a0);
        ab_out[(n * 4 + g) * 3 + 2] = pk(a1, a1);
    }

    // kk-major Whh layout: idx = kk*512 + g*128 + n  ->  {w(2kk), w(2kk+1)}
    for (int i = idx0; i < 2 * 32768; i += stride) {
        int which = i >= 32768;
        int idx = i & 32767;
        const float* Whh = which ? Whh_d : Whh_e;
        float2* out = which ? g_wsD : g_wsE;
        int n = idx & 127;
        int g = (idx >> 7) & 3;
        int kk = idx >> 9;
        float w0 = Whh[(g * 128 + n) * 128 + 2 * kk + 0];
        float w1 = Whh[(g * 128 + n) * 128 + 2 * kk + 1];
        out[idx] = make_float2(w0, w1);
    }

    // MLP weight transposes
    for (int j = idx0; j < 128 * 256; j += stride) {
        int k = j >> 8, mc = j & 255;
        g_Wm1T[j] = Wm1[mc * 128 + k];
    }
    for (int j = idx0; j < 256 * 112; j += stride) {
        int k = j / 112, mc = j % 112;
        g_Wm2T[j] = Wm2[mc * 256 + k];
    }
}

// ---------------- main persistent kernel ---------------------------------------
// 512 threads, 56 rows (28 pairs) per block. thread: n = tid&127, slot = tid>>7.
// Each slot owns 7 pairs. h, c pair-packed in smem: [pair][k] float2.

#define ROWS  56
#define NPAIR 28
#define JPT   7
#define TMAX  50

// smem layout (bytes):
//  hbuf0 : 0       28672
//  hbuf1 : 28672   28672
//  c_s   : 57344   28672
//  ab_s  : 86016   12288
//  offx  : 98304   11200
//  offy  : 109504  11200
//  base_s: 120704  512     (56 float2)
//  offc  : 121216  512     (x[56], y[56] floats)
//  wr_s  : 121728  1024
//  mbar  : 122752  128     (3 x 8B mbarriers, padded)
//  wstage: 122880  98304   (3 x 32KB weight chunk buffers; m1_s aliases here)
#define MBAR_OFF   122752
#define WSTAGE_OFF 122880
#define SMEM_BYTES 221184

__device__ __forceinline__ void lstm_step(
    const float2* __restrict__ hin, float2* __restrict__ hout,
    float2* __restrict__ c_s, const ull* __restrict__ ab_s,
    const float2* __restrict__ wd,      // gmem weights, [kk][g][n] float2
    float2* __restrict__ wstage,        // smem, 3 buffers of 4096 float2
    uint32_t mbar_base, int* ph,
    const ull* __restrict__ offx, const ull* __restrict__ offy,
    int n, int slot, int tid)
{
    ull acc[4][JPT];
    {
        ull bb[4], a0[4], a1[4];
#pragma unroll
        for (int g = 0; g < 4; g++) {
            const ull* q = &ab_s[(n * 4 + g) * 3];
            bb[g] = q[0]; a0[g] = q[1]; a1[g] = q[2];
        }
#pragma unroll
        for (int j = 0; j < JPT; j++) {
            int p = slot * JPT + j;
            ull ox = offx[p], oy = offy[p];
#pragma unroll
            for (int g = 0; g < 4; g++)
                acc[g][j] = f2fma(a0[g], ox, f2fma(a1[g], oy, bb[g]));
        }
    }

    const uint32_t ws_base = (uint32_t)__cvta_generic_to_shared(wstage);

    // prologue: one thread fences the proxy crossing and TMA-issues chunks 0,1.
    // Safe: caller guarantees a __syncthreads since the last generic write /
    // read of the staging region.
    if (tid == 0) {
        asm volatile("fence.proxy.async.shared::cta;" ::: "memory");
#pragma unroll
        for (int c0 = 0; c0 < 2; c0++)
            mbar_expect_bulk(mbar_base + c0 * 8, ws_base + c0 * 32768u,
                             (const char*)wd + (size_t)c0 * 32768, 32768u);
    }

    const float2* hp = hin + (size_t)slot * JPT * 128;

#pragma unroll 1
    for (int c = 0; c < 8; c++) {
        int b = c % 3;
        if (tid == 0) {
            mbar_wait(mbar_base + b * 8, ph[b]);
            ph[b] ^= 1;
        }
        __syncthreads();
        // issue chunk c+2 into buffer (c+2)%3 — its last readers (chunk c-1)
        // all passed the barrier above.
        if (tid == 0 && c < 6) {
            int nb = (c + 2) % 3;
            mbar_expect_bulk(mbar_base + nb * 8, ws_base + nb * 32768u,
                             (const char*)wd + (size_t)(c + 2) * 32768, 32768u);
        }

        const float2* wb = wstage + b * 4096;
#pragma unroll
        for (int kkl = 0; kkl < 8; kkl++) {
            int kk = c * 8 + kkl;
            // conflict-free LDS.64 per gate: lane stride 8B
            float2 w[4];
#pragma unroll
            for (int g = 0; g < 4; g++)
                w[g] = wb[((kkl * 4 + g) << 7) + n];
            ull wa[4], wv[4];
#pragma unroll
            for (int g = 0; g < 4; g++) {
                wa[g] = pk(w[g].x, w[g].x);
                wv[g] = pk(w[g].y, w[g].y);
            }
#pragma unroll
            for (int j = 0; j < JPT; j++) {
                ulonglong2 hv = *(const ulonglong2*)(hp + j * 128 + 2 * kk);
#pragma unroll
                for (int g = 0; g < 4; g++) {
                    acc[g][j] = f2fma(wa[g], hv.x, acc[g][j]);
                    acc[g][j] = f2fma(wv[g], hv.y, acc[g][j]);
                }
            }
        }
    }

#pragma unroll
    for (int j = 0; j < JPT; j++) {
        int p = slot * JPT + j;
        float2 iv = unpk(acc[0][j]);
        float2 fv = unpk(acc[1][j]);
        float2 gv = unpk(acc[2][j]);
        float2 ov = unpk(acc[3][j]);
        float2 cv = c_s[p * 128 + n];
        float c0 = sigma_(fv.x) * cv.x + sigma_(iv.x) * tanha_(gv.x);
        float c1 = sigma_(fv.y) * cv.y + sigma_(iv.y) * tanha_(gv.y);
        c_s[p * 128 + n] = make_float2(c0, c1);
        hout[p * 128 + n] = make_float2(sigma_(ov.x) * tanha_(c0),
                                        sigma_(ov.y) * tanha_(c1));
    }
}

__global__ void __launch_bounds__(512, 1)
k_main(const float* __restrict__ obs, const float* __restrict__ bm1,
       const float* __restrict__ bm2, const float* __restrict__ Wr,
       const float* __restrict__ br, const float* __restrict__ z,
       float* __restrict__ out, int B, int T, int S)
{
    extern __shared__ char smem[];
    float2* hbuf0 = (float2*)smem;
    float2* hbuf1 = (float2*)(smem + 28672);
    float2* c_s   = (float2*)(smem + 57344);
    ull*    ab_s  = (ull*)(smem + 86016);
    ull*    offx_s = (ull*)(smem + 98304);
    ull*    offy_s = (ull*)(smem + 109504);
    float2* base_s = (float2*)(smem + 120704);
    float*  offc   = (float*)(smem + 121216);   // x[56], y[56]
    float*  wr_s   = (float*)(smem + 121728);   // 256
    float2* wstage = (float2*)(smem + WSTAGE_OFF);
    float2* m1_s   = wstage;                    // aliased: MLP phase only

    const int tid = threadIdx.x;
    const int n = tid & 127;
    const int slot = tid >> 7;
    const int b0 = blockIdx.x * ROWS;
    if (T > TMAX) T = TMAX;

    const uint32_t mbar_base =
        (uint32_t)__cvta_generic_to_shared(smem + MBAR_OFF);
    int ph[3] = {0, 0, 0};

    // ---- init: mbarriers, zero h0/c0, encoder folded weights, offsets ----
    if (tid == 0) {
#pragma unroll
        for (int b = 0; b < 3; b++)
            asm volatile("mbarrier.init.shared.b64 [%0], %1;"
                         :: "r"(mbar_base + b * 8), "r"(1) : "memory");
    }
    for (int i = tid; i < NPAIR * 128; i += 512) {
        hbuf0[i] = make_float2(0.f, 0.f);
        c_s[i] = make_float2(0.f, 0.f);
    }
    for (int i = tid; i < 1536; i += 512) ab_s[i] = g_abE[i];
    if (tid < 256) wr_s[tid] = Wr[tid];

    for (int i = tid; i < ROWS * T; i += 512) {
        int r = i / T, t = i % T;
        int b = b0 + r;
        float ox = 0.f, oy = 0.f;
        float cx = 0.f, cy = 0.f;
        if (b < B) {
            cx = obs[((size_t)b * T + t) * 2 + 0];
            cy = obs[((size_t)b * T + t) * 2 + 1];
            float px = 0.f, py = 0.f;
            if (t > 0) {
                px = obs[((size_t)b * T + t - 1) * 2 + 0];
                py = obs[((size_t)b * T + t - 1) * 2 + 1];
            }
            ox = cx - px; oy = cy - py;
        }
        if (t == T - 1) base_s[r] = make_float2(cx, cy);
        ((float*)&offx_s[t * NPAIR + (r >> 1)])[r & 1] = ox;
        ((float*)&offy_s[t * NPAIR + (r >> 1)])[r & 1] = oy;
    }
    __syncthreads();

    float2* bufs[2] = {hbuf0, hbuf1};
    int par = 0;

    // ---- encoder ----
    for (int t = 0; t < T; t++) {
        lstm_step(bufs[par], bufs[par ^ 1], c_s, ab_s, g_wsE, wstage,
                  mbar_base, ph, &offx_s[t * NPAIR], &offy_s[t * NPAIR],
                  n, slot, tid);
        __syncthreads();
        par ^= 1;
    }

    // ---- save last offsets (decoder init input) + swap to decoder weights ----
    if (tid < NPAIR) {
        ((ull*)offc)[tid]          = offx_s[(T - 1) * NPAIR + tid];
        ((ull*)(offc + ROWS))[tid] = offy_s[(T - 1) * NPAIR + tid];
    }
    for (int i = tid; i < 1536; i += 512) ab_s[i] = g_abD[i];
    __syncthreads();

    // ---- MLP layer 1: m1 = relu(Wm1 @ hF + bm1) (outs n and n+128) ----
    {
        const float2* hf = bufs[par];
        ull acc1[2][JPT];
        float b0f = bm1[n], b1f = bm1[n + 128];
#pragma unroll
        for (int j = 0; j < JPT; j++) { acc1[0][j] = pk(b0f, b0f); acc1[1][j] = pk(b1f, b1f); }
        const float2* hp = hf + (size_t)slot * JPT * 128;
        for (int kk = 0; kk < 64; kk++) {
            float wA0 = g_Wm1T[(2 * kk) * 256 + n];
            float wA1 = g_Wm1T[(2 * kk + 1) * 256 + n];
            float wB0 = g_Wm1T[(2 * kk) * 256 + n + 128];
            float wB1 = g_Wm1T[(2 * kk + 1) * 256 + n + 128];
            ull w00 = pk(wA0, wA0), w01 = pk(wA1, wA1);
            ull w10 = pk(wB0, wB0), w11 = pk(wB1, wB1);
#pragma unroll
            for (int j = 0; j < JPT; j++) {
                ulonglong2 hv = *(const ulonglong2*)(hp + j * 128 + 2 * kk);
                acc1[0][j] = f2fma(w00, hv.x, acc1[0][j]);
                acc1[0][j] = f2fma(w01, hv.y, acc1[0][j]);
                acc1[1][j] = f2fma(w10, hv.x, acc1[1][j]);
                acc1[1][j] = f2fma(w11, hv.y, acc1[1][j]);
            }
        }
        __syncthreads();  // staging region quiesced before m1_s overwrite
#pragma unroll
        for (int j = 0; j < JPT; j++) {
            int p = slot * JPT + j;
            float2 v0 = unpk(acc1[0][j]);
            float2 v1 = unpk(acc1[1][j]);
            m1_s[p * 256 + n]       = make_float2(fmaxf(v0.x, 0.f), fmaxf(v0.y, 0.f));
            m1_s[p * 256 + n + 128] = make_float2(fmaxf(v1.x, 0.f), fmaxf(v1.y, 0.f));
        }
    }
    __syncthreads();

    // ---- MLP layer 2 + concat(z) -> dh written into bufs[par]; reset c ----
    {
        float2* hwr = bufs[par];
        if (n < 112) {
            ull acc2[JPT];
            float bb2 = bm2[n];
#pragma unroll
            for (int j = 0; j < JPT; j++) acc2[j] = pk(bb2, bb2);
            const float2* mp = m1_s + (size_t)slot * JPT * 256;
            for (int kk = 0; kk < 128; kk++) {
                float w0 = g_Wm2T[(2 * kk) * 112 + n];
                float w1 = g_Wm2T[(2 * kk + 1) * 112 + n];
                ull W0 = pk(w0, w0), W1 = pk(w1, w1);
#pragma unroll
                for (int j = 0; j < JPT; j++) {
                    ulonglong2 mv = *(const ulonglong2*)(mp + j * 256 + 2 * kk);
                    acc2[j] = f2fma(W0, mv.x, acc2[j]);
                    acc2[j] = f2fma(W1, mv.y, acc2[j]);
                }
            }
#pragma unroll
            for (int j = 0; j < JPT; j++) {
                int p = slot * JPT + j;
                float2 v = unpk(acc2[j]);
                hwr[p * 128 + n] = make_float2(fmaxf(v.x, 0.f), fmaxf(v.y, 0.f));
            }
        }
        {   // z concat: thread -> (pair, zz)
            int p = tid >> 4, zz = tid & 15;
            if (p < NPAIR) {
                int r0 = b0 + 2 * p, r1 = r0 + 1;
                float z0 = (r0 < B) ? z[(size_t)r0 * 16 + zz] : 0.f;
                float z1 = (r1 < B) ? z[(size_t)r1 * 16 + zz] : 0.f;
                hwr[p * 128 + 112 + zz] = make_float2(z0, z1);
            }
        }
        for (int i = tid; i < NPAIR * 128; i += 512) c_s[i] = make_float2(0.f, 0.f);
    }
    __syncthreads();

    // ---- decoder ----
    const int wwid = tid >> 5, lid = tid & 31;
    const int row_l = 4 * wwid + (lid >> 3);          // 0..63
    const bool row_ok = (row_l < ROWS);
    const int row_c = row_ok ? row_l : 0;
    const int kb = lid & 7;
    const bool rlead = row_ok && ((lid & 7) == 0);
    float2 mybase = base_s[row_c];
    float2 oacc = make_float2(0.f, 0.f);
    float br0 = br[0], br1 = br[1];

    for (int s = 0; s < S; s++) {
        lstm_step(bufs[par], bufs[par ^ 1], c_s, ab_s, g_wsD, wstage,
                  mbar_base, ph, (const ull*)offc, (const ull*)(offc + ROWS),
                  n, slot, tid);
        __syncthreads();
        // readout: off = Wr @ h_new + br ; cumsum output
        const float* hv2 = (const float*)bufs[par ^ 1];
        float p0 = 0.f, p1 = 0.f;
        int bidx = (row_c >> 1) * 256 + (row_c & 1);
#pragma unroll 4
        for (int m = 0; m < 16; m++) {
            int k = kb + 8 * m;
            float hvv = hv2[bidx + 2 * k];
            p0 += wr_s[k] * hvv;
            p1 += wr_s[128 + k] * hvv;
        }
        p0 += __shfl_xor_sync(0xffffffffu, p0, 1);
        p0 += __shfl_xor_sync(0xffffffffu, p0, 2);
        p0 += __shfl_xor_sync(0xffffffffu, p0, 4);
        p1 += __shfl_xor_sync(0xffffffffu, p1, 1);
        p1 += __shfl_xor_sync(0xffffffffu, p1, 2);
        p1 += __shfl_xor_sync(0xffffffffu, p1, 4);
        if (rlead) {
            float ox = p0 + br0, oy = p1 + br1;
            oacc.x += ox; oacc.y += oy;
            offc[row_l] = ox;
            offc[ROWS + row_l] = oy;
            int b = b0 + row_l;
            if (b < B) {
                out[((size_t)b * S + s) * 2 + 0] = mybase.x + oacc.x;
                out[((size_t)b * S + s) * 2 + 1] = mybase.y + oacc.y;
            }
        }
        __syncthreads();
        par ^= 1;
    }
}

// ---------------- launch ------------------------------------------------------
extern "C" void kernel_launch(void* const* d_in, const int* in_sizes, int n_in,
                              void* d_out, int out_size) {
    const float* obs   = (const float*)d_in[0];
    const float* We    = (const float*)d_in[2];
    const float* be    = (const float*)d_in[3];
    const float* Wih_e = (const float*)d_in[4];
    const float* Whh_e = (const float*)d_in[5];
    const float* b_e   = (const float*)d_in[6];
    const float* Wm1   = (const float*)d_in[7];
    const float* bm1   = (const float*)d_in[8];
    const float* Wm2   = (const float*)d_in[9];
    const float* bm2   = (const float*)d_in[10];
    const float* Wd    = (const float*)d_in[11];
    const float* bd    = (const float*)d_in[12];
    const float* Wih_d = (const float*)d_in[13];
    const float* Whh_d = (const float*)d_in[14];
    const float* b_d   = (const float*)d_in[15];
    const float* Wr    = (const float*)d_in[16];
    const float* br    = (const float*)d_in[17];
    const float* z     = (const float*)d_in[18];
    float* out = (float*)d_out;

    int NZ = 16;
    int B = in_sizes[18] / NZ;
    int T = in_sizes[0] / (B * 2);
    int S = out_size / (B * 2);
    int E = in_sizes[2] / 2;

    k_prep<<<256, 256>>>(Wih_e, We, be, b_e, Wih_d, Wd, bd, b_d,
                         Whh_e, Whh_d, Wm1, Wm2, E);

    cudaFuncSetAttribute(k_main, cudaFuncAttributeMaxDynamicSharedMemorySize, SMEM_BYTES);
    int grid = (B + ROWS - 1) / ROWS;
    k_main<<<grid, 512, SMEM_BYTES>>>(obs, bm1, bm2, Wr, br, z, out, B, T, S);
}

// round 12
// speedup vs baseline: 1.5646x; 1.5646x over previous
#include <cuda_runtime.h>
#include <cuda_bf16.h>
#include <cstdint>

typedef unsigned long long ull;

// ---------------- device-global scratch (no runtime alloc allowed) -------------
// Weight tables, kk-major: idx = kk*512 + g*128 + n -> float2 {w(2kk), w(2kk+1)}
// (256KB each; conflict-free LDS.64 per (kk,g) across lanes n)
__device__ float2 g_wsE[64 * 4 * 128];
__device__ float2 g_wsD[64 * 4 * 128];
__device__ float  g_abE[512 * 3];          // per (n,g): bias, a0, a1 (floats)
__device__ float  g_abD[512 * 3];
__device__ float  g_Wm1T[128 * 256];       // [k][mc]
__device__ float  g_Wm2T[256 * 112];       // [k][mc]

// ---------------- f32x2 + async helpers ----------------------------------------
__device__ __forceinline__ ull f2fma(ull a, ull b, ull c) {
    ull d;
    asm("fma.rn.f32x2 %0, %1, %2, %3;" : "=l"(d) : "l"(a), "l"(b), "l"(c));
    return d;
}
__device__ __forceinline__ ull pk(float lo, float hi) {
    ull r;
    asm("mov.b64 %0, {%1, %2};" : "=l"(r) : "f"(lo), "f"(hi));
    return r;
}
__device__ __forceinline__ float2 unpk(ull v) {
    float2 r;
    asm("mov.b64 {%0, %1}, %2;" : "=f"(r.x), "=f"(r.y) : "l"(v));
    return r;
}
__device__ __forceinline__ void cp_async16(uint32_t saddr, const void* gptr) {
    asm volatile("cp.async.cg.shared.global [%0], [%1], 16;" :: "r"(saddr), "l"(gptr));
}
// HW tanh (MUFU.TANH). sigmoid(x) = 0.5*tanh(x/2) + 0.5
__device__ __forceinline__ float tanha_(float x) {
    float r;
    asm("tanh.approx.f32 %0, %1;" : "=f"(r) : "f"(x));
    return r;
}
__device__ __forceinline__ float sigma_(float x) {
    return fmaf(0.5f, tanha_(0.5f * x), 0.5f);
}

// ---------------- fused precompute kernel --------------------------------------
__global__ void k_prep(const float* __restrict__ Wih_e, const float* __restrict__ We,
                       const float* __restrict__ be,   const float* __restrict__ b_e,
                       const float* __restrict__ Wih_d, const float* __restrict__ Wd,
                       const float* __restrict__ bd,   const float* __restrict__ b_d,
                       const float* __restrict__ Whh_e, const float* __restrict__ Whh_d,
                       const float* __restrict__ Wm1,  const float* __restrict__ Wm2,
                       int E)
{
    int idx0 = blockIdx.x * blockDim.x + threadIdx.x;
    int stride = gridDim.x * blockDim.x;

    // fold A = Wih @ Win (512x2), bias = Wih @ bin + bgate  (encoder + decoder)
    for (int i = idx0; i < 1024; i += stride) {
        int which = i >> 9;          // 0 = enc, 1 = dec
        int gn = i & 511;
        const float* Wih = which ? Wih_d : Wih_e;
        const float* Win = which ? Wd : We;
        const float* bin = which ? bd : be;
        const float* bg  = which ? b_d : b_e;
        float* ab_out = which ? g_abD : g_abE;
        float a0 = 0.f, a1 = 0.f, bb = 0.f;
        for (int e = 0; e < E; e++) {
            float w = Wih[gn * E + e];
            a0 += w * Win[e * 2 + 0];
            a1 += w * Win[e * 2 + 1];
            bb += w * bin[e];
        }
        bb += bg[gn];
        int n = gn & 127, g = gn >> 7;
        ab_out[(n * 4 + g) * 3 + 0] = bb;
        ab_out[(n * 4 + g) * 3 + 1] = a0;
        ab_out[(n * 4 + g) * 3 + 2] = a1;
    }

    // kk-major Whh layout: idx = kk*512 + g*128 + n  ->  {w(2kk), w(2kk+1)}
    for (int i = idx0; i < 2 * 32768; i += stride) {
        int which = i >= 32768;
        int idx = i & 32767;
        const float* Whh = which ? Whh_d : Whh_e;
        float2* out = which ? g_wsD : g_wsE;
        int n = idx & 127;
        int g = (idx >> 7) & 3;
        int kk = idx >> 9;
        float w0 = Whh[(g * 128 + n) * 128 + 2 * kk + 0];
        float w1 = Whh[(g * 128 + n) * 128 + 2 * kk + 1];
        out[idx] = make_float2(w0, w1);
    }

    // MLP weight transposes
    for (int j = idx0; j < 128 * 256; j += stride) {
        int k = j >> 8, mc = j & 255;
        g_Wm1T[j] = Wm1[mc * 128 + k];
    }
    for (int j = idx0; j < 256 * 112; j += stride) {
        int k = j / 112, mc = j % 112;
        g_Wm2T[j] = Wm2[mc * 256 + k];
    }
}

// ---------------- main persistent kernel ---------------------------------------
// 256 threads, 28 rows (14 pairs) per CTA, 2 CTAs/SM. thread: n = tid&127,
// slot = tid>>7 (0..1), slot owns 7 pairs. h, c pair-packed in smem.

#define THREADS 256
#define ROWS  28
#define NPAIR 14
#define JPT   7
#define TMAX  50
#define NCHUNK 16         // 16 chunks x 16KB per step
#define CHUNK_F2 2048     // float2 per chunk
#define CHUNK_KK 4        // kk groups per chunk

// smem layout (bytes):
//  hbuf0 : 0      14336
//  hbuf1 : 14336  14336
//  c_s   : 28672  14336
//  offx  : 43008  5600    (TMAX*NPAIR ull)
//  offy  : 48608  5600
//  base_s: 54208  224     (28 float2)
//  offc  : 54432  224     (x[28], y[28] floats)
//  wr_s  : 54656  1024
//  ab_s  : 55680  6144    (512*3 floats)
//  wstage: 61824  49152   (3 x 16KB chunk buffers; m1_s aliases here, 28KB)
#define WSTAGE_OFF 61824
#define SMEM_BYTES 110976

__device__ __forceinline__ void lstm_step(
    const float2* __restrict__ hin, float2* __restrict__ hout,
    float2* __restrict__ c_s, const float* __restrict__ ab_s,
    const float2* __restrict__ wd,      // gmem weights, [kk][g][n] float2
    float2* __restrict__ wstage,        // smem, 3 buffers of 2048 float2
    const ull* __restrict__ offx, const ull* __restrict__ offy,
    int n, int slot, int tid)
{
    ull acc[4][JPT];
    {
        ull bb[4], a0[4], a1[4];
#pragma unroll
        for (int g = 0; g < 4; g++) {
            const float* q = &ab_s[(n * 4 + g) * 3];
            bb[g] = pk(q[0], q[0]);
            a0[g] = pk(q[1], q[1]);
            a1[g] = pk(q[2], q[2]);
        }
#pragma unroll
        for (int j = 0; j < JPT; j++) {
            int p = slot * JPT + j;
            ull ox = offx[p], oy = offy[p];
#pragma unroll
            for (int g = 0; g < 4; g++)
                acc[g][j] = f2fma(a0[g], ox, f2fma(a1[g], oy, bb[g]));
        }
    }

    const uint32_t ws_base = (uint32_t)__cvta_generic_to_shared(wstage);

    // prologue: issue chunks 0,1 (each 16KB: 1024 x 16B, 4 per thread).
    // Safe: caller guarantees a __syncthreads since the previous step's compute.
#pragma unroll
    for (int c0 = 0; c0 < 2; c0++) {
        const char* src = (const char*)(wd + c0 * CHUNK_F2) + tid * 16;
        uint32_t dst = ws_base + c0 * 16384 + tid * 16;
#pragma unroll
        for (int k = 0; k < 4; k++)
            cp_async16(dst + k * 4096, src + k * 4096);
        asm volatile("cp.async.commit_group;" ::: "memory");
    }

    const float2* hp = hin + (size_t)slot * JPT * 128;

    int buf = 0;           // buffer of chunk c (c % 3)
    int nbuf = 2;          // buffer for chunk c+2
#pragma unroll 1
    for (int c = 0; c < NCHUNK; c++) {
        if (c < NCHUNK - 1) {
            asm volatile("cp.async.wait_group 1;" ::: "memory");
        } else {
            asm volatile("cp.async.wait_group 0;" ::: "memory");
        }
        __syncthreads();
        // issue chunk c+2 into buffer (c+2)%3 — its last readers (chunk c-1)
        // all passed the barrier above.
        if (c < NCHUNK - 2) {
            const char* src = (const char*)(wd + (c + 2) * CHUNK_F2) + tid * 16;
            uint32_t dst = ws_base + nbuf * 16384 + tid * 16;
#pragma unroll
            for (int k = 0; k < 4; k++)
                cp_async16(dst + k * 4096, src + k * 4096);
            asm volatile("cp.async.commit_group;" ::: "memory");
        }

        const float2* wb = wstage + buf * CHUNK_F2;
#pragma unroll
        for (int kkl = 0; kkl < CHUNK_KK; kkl++) {
            int kk = c * CHUNK_KK + kkl;
            // conflict-free LDS.64 per gate: lane stride 8B
            float2 w[4];
#pragma unroll
            for (int g = 0; g < 4; g++)
                w[g] = wb[((kkl * 4 + g) << 7) + n];
            ull wa[4], wv[4];
#pragma unroll
            for (int g = 0; g < 4; g++) {
                wa[g] = pk(w[g].x, w[g].x);
                wv[g] = pk(w[g].y, w[g].y);
            }
#pragma unroll
            for (int j = 0; j < JPT; j++) {
                ulonglong2 hv = *(const ulonglong2*)(hp + j * 128 + 2 * kk);
#pragma unroll
                for (int g = 0; g < 4; g++) {
                    acc[g][j] = f2fma(wa[g], hv.x, acc[g][j]);
                    acc[g][j] = f2fma(wv[g], hv.y, acc[g][j]);
                }
            }
        }
        buf = (buf == 2) ? 0 : buf + 1;
        nbuf = (nbuf == 2) ? 0 : nbuf + 1;
    }

#pragma unroll
    for (int j = 0; j < JPT; j++) {
        int p = slot * JPT + j;
        float2 iv = unpk(acc[0][j]);
        float2 fv = unpk(acc[1][j]);
        float2 gv = unpk(acc[2][j]);
        float2 ov = unpk(acc[3][j]);
        float2 cv = c_s[p * 128 + n];
        float c0 = sigma_(fv.x) * cv.x + sigma_(iv.x) * tanha_(gv.x);
        float c1 = sigma_(fv.y) * cv.y + sigma_(iv.y) * tanha_(gv.y);
        c_s[p * 128 + n] = make_float2(c0, c1);
        hout[p * 128 + n] = make_float2(sigma_(ov.x) * tanha_(c0),
                                        sigma_(ov.y) * tanha_(c1));
    }
}

__global__ void __launch_bounds__(THREADS, 2)
k_main(const float* __restrict__ obs, const float* __restrict__ bm1,
       const float* __restrict__ bm2, const float* __restrict__ Wr,
       const float* __restrict__ br, const float* __restrict__ z,
       float* __restrict__ out, int B, int T, int S)
{
    extern __shared__ char smem[];
    float2* hbuf0 = (float2*)smem;
    float2* hbuf1 = (float2*)(smem + 14336);
    float2* c_s   = (float2*)(smem + 28672);
    ull*    offx_s = (ull*)(smem + 43008);
    ull*    offy_s = (ull*)(smem + 48608);
    float2* base_s = (float2*)(smem + 54208);
    float*  offc   = (float*)(smem + 54432);    // x[28], y[28]
    float*  wr_s   = (float*)(smem + 54656);    // 256
    float*  ab_s   = (float*)(smem + 55680);    // 1536 floats
    float2* wstage = (float2*)(smem + WSTAGE_OFF);
    float2* m1_s   = wstage;                    // aliased: MLP phase only (28KB)

    const int tid = threadIdx.x;
    const int n = tid & 127;
    const int slot = tid >> 7;                  // 0..1
    const int b0 = blockIdx.x * ROWS;
    if (T > TMAX) T = TMAX;

    // ---- init: zero h0/c0, load encoder folded weights, build offsets ----
    for (int i = tid; i < NPAIR * 128; i += THREADS) {
        hbuf0[i] = make_float2(0.f, 0.f);
        c_s[i] = make_float2(0.f, 0.f);
    }
    for (int i = tid; i < 1536; i += THREADS) ab_s[i] = g_abE[i];
    wr_s[tid] = Wr[tid];

    for (int i = tid; i < ROWS * T; i += THREADS) {
        int r = i / T, t = i % T;
        int b = b0 + r;
        float ox = 0.f, oy = 0.f;
        float cx = 0.f, cy = 0.f;
        if (b < B) {
            cx = obs[((size_t)b * T + t) * 2 + 0];
            cy = obs[((size_t)b * T + t) * 2 + 1];
            float px = 0.f, py = 0.f;
            if (t > 0) {
                px = obs[((size_t)b * T + t - 1) * 2 + 0];
                py = obs[((size_t)b * T + t - 1) * 2 + 1];
            }
            ox = cx - px; oy = cy - py;
        }
        if (t == T - 1) base_s[r] = make_float2(cx, cy);
        ((float*)&offx_s[t * NPAIR + (r >> 1)])[r & 1] = ox;
        ((float*)&offy_s[t * NPAIR + (r >> 1)])[r & 1] = oy;
    }
    __syncthreads();

    float2* bufs[2] = {hbuf0, hbuf1};
    int par = 0;

    // ---- encoder ----
    for (int t = 0; t < T; t++) {
        lstm_step(bufs[par], bufs[par ^ 1], c_s, ab_s, g_wsE, wstage,
                  &offx_s[t * NPAIR], &offy_s[t * NPAIR], n, slot, tid);
        __syncthreads();
        par ^= 1;
    }

    // ---- save last offsets (decoder init input) + swap to decoder weights ----
    if (tid < NPAIR) {
        ((ull*)offc)[tid]          = offx_s[(T - 1) * NPAIR + tid];
        ((ull*)(offc + ROWS))[tid] = offy_s[(T - 1) * NPAIR + tid];
    }
    for (int i = tid; i < 1536; i += THREADS) ab_s[i] = g_abD[i];
    __syncthreads();

    // ---- MLP layer 1: m1 = relu(Wm1 @ hF + bm1) (outs n and n+128) ----
    {
        const float2* hf = bufs[par];
        ull acc1[2][JPT];
        float b0f = bm1[n], b1f = bm1[n + 128];
#pragma unroll
        for (int j = 0; j < JPT; j++) { acc1[0][j] = pk(b0f, b0f); acc1[1][j] = pk(b1f, b1f); }
        const float2* hp = hf + (size_t)slot * JPT * 128;
        for (int kk = 0; kk < 64; kk++) {
            float wA0 = g_Wm1T[(2 * kk) * 256 + n];
            float wA1 = g_Wm1T[(2 * kk + 1) * 256 + n];
            float wB0 = g_Wm1T[(2 * kk) * 256 + n + 128];
            float wB1 = g_Wm1T[(2 * kk + 1) * 256 + n + 128];
            ull w00 = pk(wA0, wA0), w01 = pk(wA1, wA1);
            ull w10 = pk(wB0, wB0), w11 = pk(wB1, wB1);
#pragma unroll
            for (int j = 0; j < JPT; j++) {
                ulonglong2 hv = *(const ulonglong2*)(hp + j * 128 + 2 * kk);
                acc1[0][j] = f2fma(w00, hv.x, acc1[0][j]);
                acc1[0][j] = f2fma(w01, hv.y, acc1[0][j]);
                acc1[1][j] = f2fma(w10, hv.x, acc1[1][j]);
                acc1[1][j] = f2fma(w11, hv.y, acc1[1][j]);
            }
        }
        __syncthreads();  // staging region quiesced before m1_s overwrite
#pragma unroll
        for (int j = 0; j < JPT; j++) {
            int p = slot * JPT + j;
            float2 v0 = unpk(acc1[0][j]);
            float2 v1 = unpk(acc1[1][j]);
            m1_s[p * 256 + n]       = make_float2(fmaxf(v0.x, 0.f), fmaxf(v0.y, 0.f));
            m1_s[p * 256 + n + 128] = make_float2(fmaxf(v1.x, 0.f), fmaxf(v1.y, 0.f));
        }
    }
    __syncthreads();

    // ---- MLP layer 2 + concat(z) -> dh written into bufs[par]; reset c ----
    {
        float2* hwr = bufs[par];
        if (n < 112) {
            ull acc2[JPT];
            float bb2 = bm2[n];
#pragma unroll
            for (int j = 0; j < JPT; j++) acc2[j] = pk(bb2, bb2);
            const float2* mp = m1_s + (size_t)slot * JPT * 256;
            for (int kk = 0; kk < 128; kk++) {
                float w0 = g_Wm2T[(2 * kk) * 112 + n];
                float w1 = g_Wm2T[(2 * kk + 1) * 112 + n];
                ull W0 = pk(w0, w0), W1 = pk(w1, w1);
#pragma unroll
                for (int j = 0; j < JPT; j++) {
                    ulonglong2 mv = *(const ulonglong2*)(mp + j * 256 + 2 * kk);
                    acc2[j] = f2fma(W0, mv.x, acc2[j]);
                    acc2[j] = f2fma(W1, mv.y, acc2[j]);
                }
            }
#pragma unroll
            for (int j = 0; j < JPT; j++) {
                int p = slot * JPT + j;
                float2 v = unpk(acc2[j]);
                hwr[p * 128 + n] = make_float2(fmaxf(v.x, 0.f), fmaxf(v.y, 0.f));
            }
        }
        {   // z concat: thread -> (pair, zz)
            int p = tid >> 4, zz = tid & 15;
            if (p < NPAIR) {
                int r0 = b0 + 2 * p, r1 = r0 + 1;
                float z0 = (r0 < B) ? z[(size_t)r0 * 16 + zz] : 0.f;
                float z1 = (r1 < B) ? z[(size_t)r1 * 16 + zz] : 0.f;
                hwr[p * 128 + 112 + zz] = make_float2(z0, z1);
            }
        }
        for (int i = tid; i < NPAIR * 128; i += THREADS) c_s[i] = make_float2(0.f, 0.f);
    }
    __syncthreads();

    // ---- decoder ----
    const int wwid = tid >> 5, lid = tid & 31;
    const int row_l = 4 * wwid + (lid >> 3);          // 0..31
    const bool row_ok = (row_l < ROWS);
    const int row_c = row_ok ? row_l : 0;
    const int kb = lid & 7;
    const bool rlead = row_ok && ((lid & 7) == 0);
    float2 mybase = base_s[row_c];
    float2 oacc = make_float2(0.f, 0.f);
    float br0 = br[0], br1 = br[1];

    for (int s = 0; s < S; s++) {
        lstm_step(bufs[par], bufs[par ^ 1], c_s, ab_s, g_wsD, wstage,
                  (const ull*)offc, (const ull*)(offc + ROWS), n, slot, tid);
        __syncthreads();
        // readout: off = Wr @ h_new + br ; cumsum output
        const float* hv2 = (const float*)bufs[par ^ 1];
        float p0 = 0.f, p1 = 0.f;
        int bidx = (row_c >> 1) * 256 + (row_c & 1);
#pragma unroll 4
        for (int m = 0; m < 16; m++) {
            int k = kb + 8 * m;
            float hvv = hv2[bidx + 2 * k];
            p0 += wr_s[k] * hvv;
            p1 += wr_s[128 + k] * hvv;
        }
        p0 += __shfl_xor_sync(0xffffffffu, p0, 1);
        p0 += __shfl_xor_sync(0xffffffffu, p0, 2);
        p0 += __shfl_xor_sync(0xffffffffu, p0, 4);
        p1 += __shfl_xor_sync(0xffffffffu, p1, 1);
        p1 += __shfl_xor_sync(0xffffffffu, p1, 2);
        p1 += __shfl_xor_sync(0xffffffffu, p1, 4);
        if (rlead) {
            float ox = p0 + br0, oy = p1 + br1;
            oacc.x += ox; oacc.y += oy;
            offc[row_l] = ox;
            offc[ROWS + row_l] = oy;
            int b = b0 + row_l;
            if (b < B) {
                out[((size_t)b * S + s) * 2 + 0] = mybase.x + oacc.x;
                out[((size_t)b * S + s) * 2 + 1] = mybase.y + oacc.y;
            }
        }
        __syncthreads();
        par ^= 1;
    }
}

// ---------------- launch ------------------------------------------------------
extern "C" void kernel_launch(void* const* d_in, const int* in_sizes, int n_in,
                              void* d_out, int out_size) {
    const float* obs   = (const float*)d_in[0];
    const float* We    = (const float*)d_in[2];
    const float* be    = (const float*)d_in[3];
    const float* Wih_e = (const float*)d_in[4];
    const float* Whh_e = (const float*)d_in[5];
    const float* b_e   = (const float*)d_in[6];
    const float* Wm1   = (const float*)d_in[7];
    const float* bm1   = (const float*)d_in[8];
    const float* Wm2   = (const float*)d_in[9];
    const float* bm2   = (const float*)d_in[10];
    const float* Wd    = (const float*)d_in[11];
    const float* bd    = (const float*)d_in[12];
    const float* Wih_d = (const float*)d_in[13];
    const float* Whh_d = (const float*)d_in[14];
    const float* b_d   = (const float*)d_in[15];
    const float* Wr    = (const float*)d_in[16];
    const float* br    = (const float*)d_in[17];
    const float* z     = (const float*)d_in[18];
    float* out = (float*)d_out;

    int NZ = 16;
    int B = in_sizes[18] / NZ;
    int T = in_sizes[0] / (B * 2);
    int S = out_size / (B * 2);
    int E = in_sizes[2] / 2;

    k_prep<<<256, 256>>>(Wih_e, We, be, b_e, Wih_d, Wd, bd, b_d,
                         Whh_e, Whh_d, Wm1, Wm2, E);

    cudaFuncSetAttribute(k_main, cudaFuncAttributeMaxDynamicSharedMemorySize, SMEM_BYTES);
    int grid = (B + ROWS - 1) / ROWS;
    k_main<<<grid, THREADS, SMEM_BYTES>>>(obs, bm1, bm2, Wr, br, z, out, B, T, S);
}

// round 14
// speedup vs baseline: 6.8700x; 4.3908x over previous
#include <cuda_runtime.h>
#include <cuda_bf16.h>
#include <cstdint>

#define ROWS 56
#define TMAX 50
#define KSTEPS 9
#define STRIDE 152            // bf16 elements per row; 304 bytes, conflict-free ldmatrix
#define SB 304

// ---- smem layout (bytes) ----
#define W_OFF 0               // 512*304 = 155648 (aliased by MLP scratch between phases)
#define H_OFF 155648          // 64*304 = 19456
#define OFFX_OFF 175104       // 56*50*4
#define OFFY_OFF 186304
#define BASE_OFF 197504       // 56 float2
#define OFFC_OFF 197952       // x[56], y[56]
#define WRS_OFF  198400       // 256 f32
#define SMEM_BYTES 199424

// ---- device-global prepped images (no runtime alloc) ----
__device__ __nv_bfloat16 g_wE[512 * STRIDE];   // [gate][k] : Whh | a0 | a1 | bias | 0pad
__device__ __nv_bfloat16 g_wD[512 * STRIDE];
__device__ float g_Wm1T[128 * 256];
__device__ float g_Wm2T[256 * 112];

// ---- helpers ----
__device__ __forceinline__ float tanha_(float x) {
    float r; asm("tanh.approx.f32 %0,%1;" : "=f"(r) : "f"(x)); return r;
}
__device__ __forceinline__ float sigma_(float x) {
    return fmaf(0.5f, tanha_(0.5f * x), 0.5f);
}
__device__ __forceinline__ void ldsm4(uint32_t& r0, uint32_t& r1, uint32_t& r2,
                                      uint32_t& r3, uint32_t addr) {
    asm volatile("ldmatrix.sync.aligned.m8n8.x4.shared.b16 {%0,%1,%2,%3},[%4];"
                 : "=r"(r0), "=r"(r1), "=r"(r2), "=r"(r3) : "r"(addr));
}
__device__ __forceinline__ void mma4(float* d, uint32_t a0, uint32_t a1, uint32_t a2,
                                     uint32_t a3, uint32_t b0, uint32_t b1) {
    asm volatile(
        "mma.sync.aligned.m16n8k16.row.col.f32.bf16.bf16.f32 "
        "{%0,%1,%2,%3},{%4,%5,%6,%7},{%8,%9},{%0,%1,%2,%3};"
        : "+f"(d[0]), "+f"(d[1]), "+f"(d[2]), "+f"(d[3])
        : "r"(a0), "r"(a1), "r"(a2), "r"(a3), "r"(b0), "r"(b1));
}

// ---- fused precompute: build bf16 W_ext images + MLP transposes ----
__global__ void k_prep(const float* __restrict__ Wih_e, const float* __restrict__ We,
                       const float* __restrict__ be,   const float* __restrict__ b_e,
                       const float* __restrict__ Wih_d, const float* __restrict__ Wd,
                       const float* __restrict__ bd,   const float* __restrict__ b_d,
                       const float* __restrict__ Whh_e, const float* __restrict__ Whh_d,
                       const float* __restrict__ Wm1,  const float* __restrict__ Wm2,
                       int E)
{
    int idx0 = blockIdx.x * blockDim.x + threadIdx.x;
    int stride = gridDim.x * blockDim.x;

    for (int i = idx0; i < 2 * 512 * STRIDE; i += stride) {
        int which = i >= 512 * STRIDE;
        int idx = which ? i - 512 * STRIDE : i;
        int gg = idx / STRIDE, k = idx % STRIDE;
        const float* Whh = which ? Whh_d : Whh_e;
        float v = 0.f;
        if (k < 128) {
            v = Whh[gg * 128 + k];
        } else if (k <= 130) {
            // fold: a0 = Wih@Win col0, a1 = col1, bias = Wih@bin + bg
            const float* Wih = which ? Wih_d : Wih_e;
            const float* Win = which ? Wd : We;
            const float* bin = which ? bd : be;
            const float* bg  = which ? b_d : b_e;
            float a0 = 0.f, a1 = 0.f, bb = 0.f;
            for (int e = 0; e < E; e++) {
                float wv = Wih[gg * E + e];
                a0 += wv * Win[e * 2 + 0];
                a1 += wv * Win[e * 2 + 1];
                bb += wv * bin[e];
            }
            bb += bg[gg];
            v = (k == 128) ? a0 : (k == 129) ? a1 : bb;
        }
        __nv_bfloat16* dst = which ? g_wD : g_wE;
        dst[gg * STRIDE + k] = __float2bfloat16(v);
    }

    for (int j = idx0; j < 128 * 256; j += stride) {
        int k = j >> 8, mc = j & 255;
        g_Wm1T[j] = Wm1[mc * 128 + k];
    }
    for (int j = idx0; j < 256 * 112; j += stride) {
        int k = j / 112, mc = j % 112;
        g_Wm2T[j] = Wm2[mc * 256 + k];
    }
}

// ---- one LSTM step: MMA + epilogue (warp-synchronous, acc in regs) ----
__device__ __forceinline__ void lstm_mma_step(
    char* smem, uint32_t a_addr, uint32_t b_addr,
    int mg, int r, int lane, float* cst)
{
    float acc[64];
#pragma unroll
    for (int i = 0; i < 64; i++) acc[i] = 0.f;

#pragma unroll 1
    for (int ks = 0; ks < KSTEPS; ks++) {
        uint32_t a0, a1, a2, a3;
        ldsm4(a0, a1, a2, a3, a_addr + ks * 32);
#pragma unroll
        for (int ty = 0; ty < 4; ty++) {
#pragma unroll
            for (int p = 0; p < 2; p++) {
                uint32_t b0, b1, b2, b3;
                // tiles T0 = 16ty+8p+r (lanes<16) and T0+4 (lanes>=16), gate rows 8T
                ldsm4(b0, b1, b2, b3, b_addr + (16 * ty + 8 * p) * 2432 + ks * 32);
                mma4(&acc[(ty * 4 + 2 * p) * 4],     a0, a1, a2, a3, b0, b1);
                mma4(&acc[(ty * 4 + 2 * p + 1) * 4], a0, a1, a2, a3, b2, b3);
            }
        }
    }

    // epilogue: thread-local i/f/g/o per (unit,row); h -> bf16 smem
#pragma unroll
    for (int j = 0; j < 4; j++) {
#pragma unroll
        for (int idx = 0; idx < 4; idx++) {
            int rh = idx >> 1, q = idx & 1;
            float pi = acc[(0 * 4 + j) * 4 + idx];
            float pf = acc[(1 * 4 + j) * 4 + idx];
            float pg = acc[(2 * 4 + j) * 4 + idx];
            float po = acc[(3 * 4 + j) * 4 + idx];
            float cn = sigma_(pf) * cst[j * 4 + idx] + sigma_(pi) * tanha_(pg);
            cst[j * 4 + idx] = cn;
            float hn = sigma_(po) * tanha_(cn);
            int row = 16 * mg + (lane >> 2) + 8 * rh;
            if (row < ROWS) {
                int u = 32 * j + 8 * r + 2 * (lane & 3) + q;
                *(__nv_bfloat16*)(smem + H_OFF + row * SB + u * 2) = __float2bfloat16(hn);
            }
        }
    }
}

// ---- main persistent kernel: 512 threads, 56 rows/CTA ----
__global__ void __launch_bounds__(512, 1)
k_main(const float* __restrict__ obs, const float* __restrict__ bm1,
       const float* __restrict__ bm2, const float* __restrict__ Wr,
       const float* __restrict__ br, const float* __restrict__ z,
       float* __restrict__ out, int B, int T, int S)
{
    extern __shared__ char smem[];
    const int tid = threadIdx.x;
    const int lane = tid & 31, w = tid >> 5;
    const int mg = w >> 2, r = w & 3;
    const int b0 = blockIdx.x * ROWS;
    if (T > TMAX) T = TMAX;

    uint32_t sbase = (uint32_t)__cvta_generic_to_shared(smem);
    float* offx_s = (float*)(smem + OFFX_OFF);
    float* offy_s = (float*)(smem + OFFY_OFF);
    float2* base_s = (float2*)(smem + BASE_OFF);
    float* offc = (float*)(smem + OFFC_OFF);
    float* wr_s = (float*)(smem + WRS_OFF);

    // ldmatrix lane address bases
    const uint32_t a_addr = sbase + H_OFF + (16 * mg + (lane & 15)) * SB + ((lane >> 4) << 4);
    const uint32_t b_addr = sbase + W_OFF + (lane & 7) * SB + (((lane >> 3) & 1) << 4)
                          + ((lane >> 4) ? 4 * 2432u : 0u) + r * 2432u;

    // ---- init: zero h_ext, const-1 col, offsets, Wr, encoder W image ----
    for (int i = tid; i < 4864; i += 512) ((uint32_t*)(smem + H_OFF))[i] = 0;
    if (tid < 256) wr_s[tid] = Wr[tid];
    for (int i = tid; i < ROWS * T; i += 512) {
        int rr = i / T, t = i % T;
        int b = b0 + rr;
        float ox = 0.f, oy = 0.f, cx = 0.f, cy = 0.f;
        if (b < B) {
            cx = obs[((size_t)b * T + t) * 2 + 0];
            cy = obs[((size_t)b * T + t) * 2 + 1];
            float px = 0.f, py = 0.f;
            if (t > 0) {
                px = obs[((size_t)b * T + t - 1) * 2 + 0];
                py = obs[((size_t)b * T + t - 1) * 2 + 1];
            }
            ox = cx - px; oy = cy - py;
        }
        if (t == T - 1) base_s[rr] = make_float2(cx, cy);
        offx_s[t * ROWS + rr] = ox;
        offy_s[t * ROWS + rr] = oy;
    }
    {
        const float4* src = (const float4*)g_wE;
        float4* dst = (float4*)(smem + W_OFF);
        for (int i = tid; i < 9728; i += 512) dst[i] = src[i];
    }
    __syncthreads();
    if (tid < ROWS)   // const-1 column (col 130) for valid rows
        *(__nv_bfloat16*)(smem + H_OFF + tid * SB + 130 * 2) = __float2bfloat16(1.0f);
    // encoder step-0 offsets into h cols 128/129
    if (tid < 112) {
        int rr = tid >> 1, c = tid & 1;
        float v = c ? offy_s[rr] : offx_s[rr];
        *(__nv_bfloat16*)(smem + H_OFF + rr * SB + (128 + c) * 2) = __float2bfloat16(v);
    }

    float cst[16];
#pragma unroll
    for (int i = 0; i < 16; i++) cst[i] = 0.f;

    // ---- encoder ----
    for (int t = 0; t < T; t++) {
        __syncthreads();
        lstm_mma_step(smem, a_addr, b_addr, mg, r, lane, cst);
        __syncthreads();
        if (t + 1 < T && tid < 112) {
            int rr = tid >> 1, c = tid & 1;
            float v = c ? offy_s[(t + 1) * ROWS + rr] : offx_s[(t + 1) * ROWS + rr];
            *(__nv_bfloat16*)(smem + H_OFF + rr * SB + (128 + c) * 2) = __float2bfloat16(v);
        }
    }
    __syncthreads();

    // ---- MLP (aliases W region: hf [0,28672), m1 [28672,86016)) ----
    {
        float* hf = (float*)(smem + W_OFF);
        float* m1 = (float*)(smem + W_OFF + 28672);
        for (int i = tid; i < ROWS * 128; i += 512) {
            int rr = i >> 7, k = i & 127;
            hf[i] = __bfloat162float(
                *(const __nv_bfloat16*)(smem + H_OFF + rr * SB + k * 2));
        }
        __syncthreads();
        {   // layer 1: m1 = relu(hf @ Wm1^T + bm1)
            int mc = tid & 255, half = tid >> 8;
            for (int rr = half * 28; rr < half * 28 + 28; rr++) {
                float acc = bm1[mc];
                const float* hr = hf + rr * 128;
#pragma unroll 8
                for (int k = 0; k < 128; k++)
                    acc = fmaf(hr[k], g_Wm1T[k * 256 + mc], acc);
                m1[rr * 256 + mc] = fmaxf(acc, 0.f);
            }
        }
        __syncthreads();
        // layer 2 -> h cols 0..111 (bf16), z concat cols 112..127
        if (tid < 448) {
            int n2 = tid % 112, rq = tid / 112;
            for (int rr = rq * 14; rr < rq * 14 + 14; rr++) {
                float acc = bm2[n2];
                const float* mr = m1 + rr * 256;
#pragma unroll 8
                for (int k = 0; k < 256; k++)
                    acc = fmaf(mr[k], g_Wm2T[k * 112 + n2], acc);
                *(__nv_bfloat16*)(smem + H_OFF + rr * SB + n2 * 2) =
                    __float2bfloat16(fmaxf(acc, 0.f));
            }
        }
        for (int i = tid; i < ROWS * 16; i += 512) {
            int rr = i >> 4, zi = i & 15;
            int b = b0 + rr;
            float zv = (b < B) ? z[(size_t)b * 16 + zi] : 0.f;
            *(__nv_bfloat16*)(smem + H_OFF + rr * SB + (112 + zi) * 2) = __float2bfloat16(zv);
        }
        // decoder initial input offsets = last encoder offsets
        if (tid < 112) {
            int rr = tid >> 1, c = tid & 1;
            float v = c ? offy_s[(T - 1) * ROWS + rr] : offx_s[(T - 1) * ROWS + rr];
            if (c == 0) offc[rr] = v; else offc[ROWS + rr] = v;
            *(__nv_bfloat16*)(smem + H_OFF + rr * SB + (128 + c) * 2) = __float2bfloat16(v);
        }
    }
    __syncthreads();
    // decoder W image (overwrites MLP scratch)
    {
        const float4* src = (const float4*)g_wD;
        float4* dst = (float4*)(smem + W_OFF);
        for (int i = tid; i < 9728; i += 512) dst[i] = src[i];
    }
#pragma unroll
    for (int i = 0; i < 16; i++) cst[i] = 0.f;

    // ---- decoder ----
    const int row = tid >> 3;        // 0..63 ; active rows < 56 (tid < 448)
    const int kb = tid & 7;
    const bool ract = (tid < 448);
    float2 mybase = ract ? base_s[row] : make_float2(0.f, 0.f);
    float2 oacc = make_float2(0.f, 0.f);
    float br0 = br[0], br1 = br[1];

    for (int s = 0; s < S; s++) {
        __syncthreads();
        lstm_mma_step(smem, a_addr, b_addr, mg, r, lane, cst);
        __syncthreads();
        if (ract) {     // readout Wr @ h + br ; cumsum ; stage next offsets
            float p0 = 0.f, p1 = 0.f;
#pragma unroll
            for (int m = 0; m < 16; m++) {
                int k = kb + 8 * m;
                float hv = __bfloat162float(
                    *(const __nv_bfloat16*)(smem + H_OFF + row * SB + k * 2));
                p0 = fmaf(wr_s[k], hv, p0);
                p1 = fmaf(wr_s[128 + k], hv, p1);
            }
            p0 += __shfl_xor_sync(0xffffffffu, p0, 1);
            p0 += __shfl_xor_sync(0xffffffffu, p0, 2);
            p0 += __shfl_xor_sync(0xffffffffu, p0, 4);
            p1 += __shfl_xor_sync(0xffffffffu, p1, 1);
            p1 += __shfl_xor_sync(0xffffffffu, p1, 2);
            p1 += __shfl_xor_sync(0xffffffffu, p1, 4);
            if (kb == 0) {
                float oxv = p0 + br0, oyv = p1 + br1;
                oacc.x += oxv; oacc.y += oyv;
                *(__nv_bfloat16*)(smem + H_OFF + row * SB + 128 * 2) = __float2bfloat16(oxv);
                *(__nv_bfloat16*)(smem + H_OFF + row * SB + 129 * 2) = __float2bfloat16(oyv);
                int b = b0 + row;
                if (b < B) {
                    out[((size_t)b * S + s) * 2 + 0] = mybase.x + oacc.x;
                    out[((size_t)b * S + s) * 2 + 1] = mybase.y + oacc.y;
                }
            }
        }
    }
}

// ---- launch ----
extern "C" void kernel_launch(void* const* d_in, const int* in_sizes, int n_in,
                              void* d_out, int out_size) {
    const float* obs   = (const float*)d_in[0];
    const float* We    = (const float*)d_in[2];
    const float* be    = (const float*)d_in[3];
    const float* Wih_e = (const float*)d_in[4];
    const float* Whh_e = (const float*)d_in[5];
    const float* b_e   = (const float*)d_in[6];
    const float* Wm1   = (const float*)d_in[7];
    const float* bm1   = (const float*)d_in[8];
    const float* Wm2   = (const float*)d_in[9];
    const float* bm2   = (const float*)d_in[10];
    const float* Wd    = (const float*)d_in[11];
    const float* bd    = (const float*)d_in[12];
    const float* Wih_d = (const float*)d_in[13];
    const float* Whh_d = (const float*)d_in[14];
    const float* b_d   = (const float*)d_in[15];
    const float* Wr    = (const float*)d_in[16];
    const float* br    = (const float*)d_in[17];
    const float* z     = (const float*)d_in[18];
    float* out = (float*)d_out;

    int NZ = 16;
    int B = in_sizes[18] / NZ;
    int T = in_sizes[0] / (B * 2);
    int S = out_size / (B * 2);
    int E = in_sizes[2] / 2;

    k_prep<<<256, 256>>>(Wih_e, We, be, b_e, Wih_d, Wd, bd, b_d,
                         Whh_e, Whh_d, Wm1, Wm2, E);

    cudaFuncSetAttribute(k_main, cudaFuncAttributeMaxDynamicSharedMemorySize, SMEM_BYTES);
    int grid = (B + ROWS - 1) / ROWS;
    k_main<<<grid, 512, SMEM_BYTES>>>(obs, bm1, bm2, Wr, br, z, out, B, T, S);
}

// round 16
// speedup vs baseline: 7.2397x; 1.0538x over previous
#include <cuda_runtime.h>
#include <cuda_bf16.h>
#include <cstdint>

#define ROWS 56
#define TMAX 50
#define KSTEPS 9
#define STRIDE 152            // bf16 elements per row; 304 bytes
#define SB 304
#define GSTRIDE (128 * SB)    // 38912 bytes between gate blocks in W image

// ---- smem layout (bytes) ----
#define W_OFF 0               // 512*304 = 155648 (aliased by MLP scratch between phases)
#define H_OFF 155648          // 64*304 = 19456
#define OFFX_OFF 175104       // 56*50*4
#define OFFY_OFF 186304
#define BASE_OFF 197504       // 56 float2
#define OFFC_OFF 197952       // x[56], y[56]
#define WRS_OFF  198400       // 256 f32
#define SMEM_BYTES 199424

// ---- device-global prepped images (no runtime alloc) ----
__device__ __nv_bfloat16 g_wE[512 * STRIDE];   // [gate][k] : Whh | a0 | a1 | bias | 0pad
__device__ __nv_bfloat16 g_wD[512 * STRIDE];
__device__ float g_Wm1T[128 * 256];
__device__ float g_Wm2T[256 * 112];

// ---- helpers ----
__device__ __forceinline__ float tanha_(float x) {
    float r; asm("tanh.approx.f32 %0,%1;" : "=f"(r) : "f"(x)); return r;
}
__device__ __forceinline__ float sigma_(float x) {
    return fmaf(0.5f, tanha_(0.5f * x), 0.5f);
}
__device__ __forceinline__ void ldsm4(uint32_t& r0, uint32_t& r1, uint32_t& r2,
                                      uint32_t& r3, uint32_t addr) {
    asm volatile("ldmatrix.sync.aligned.m8n8.x4.shared.b16 {%0,%1,%2,%3},[%4];"
                 : "=r"(r0), "=r"(r1), "=r"(r2), "=r"(r3) : "r"(addr));
}
__device__ __forceinline__ void mma4(float* d, uint32_t a0, uint32_t a1, uint32_t a2,
                                     uint32_t a3, uint32_t b0, uint32_t b1) {
    asm volatile(
        "mma.sync.aligned.m16n8k16.row.col.f32.bf16.bf16.f32 "
        "{%0,%1,%2,%3},{%4,%5,%6,%7},{%8,%9},{%0,%1,%2,%3};"
        : "+f"(d[0]), "+f"(d[1]), "+f"(d[2]), "+f"(d[3])
        : "r"(a0), "r"(a1), "r"(a2), "r"(a3), "r"(b0), "r"(b1));
}

// ---- fused precompute: build bf16 W_ext images + MLP transposes ----
__global__ void k_prep(const float* __restrict__ Wih_e, const float* __restrict__ We,
                       const float* __restrict__ be,   const float* __restrict__ b_e,
                       const float* __restrict__ Wih_d, const float* __restrict__ Wd,
                       const float* __restrict__ bd,   const float* __restrict__ b_d,
                       const float* __restrict__ Whh_e, const float* __restrict__ Whh_d,
                       const float* __restrict__ Wm1,  const float* __restrict__ Wm2,
                       int E)
{
    int idx0 = blockIdx.x * blockDim.x + threadIdx.x;
    int stride = gridDim.x * blockDim.x;

    for (int i = idx0; i < 2 * 512 * STRIDE; i += stride) {
        int which = i >= 512 * STRIDE;
        int idx = which ? i - 512 * STRIDE : i;
        int gg = idx / STRIDE, k = idx % STRIDE;
        const float* Whh = which ? Whh_d : Whh_e;
        float v = 0.f;
        if (k < 128) {
            v = Whh[gg * 128 + k];
        } else if (k <= 130) {
            const float* Wih = which ? Wih_d : Wih_e;
            const float* Win = which ? Wd : We;
            const float* bin = which ? bd : be;
            const float* bg  = which ? b_d : b_e;
            float a0 = 0.f, a1 = 0.f, bb = 0.f;
            for (int e = 0; e < E; e++) {
                float wv = Wih[gg * E + e];
                a0 += wv * Win[e * 2 + 0];
                a1 += wv * Win[e * 2 + 1];
                bb += wv * bin[e];
            }
            bb += bg[gg];
            v = (k == 128) ? a0 : (k == 129) ? a1 : bb;
        }
        __nv_bfloat16* dst = which ? g_wD : g_wE;
        dst[gg * STRIDE + k] = __float2bfloat16(v);
    }

    for (int j = idx0; j < 128 * 256; j += stride) {
        int k = j >> 8, mc = j & 255;
        g_Wm1T[j] = Wm1[mc * 128 + k];
    }
    for (int j = idx0; j < 256 * 112; j += stride) {
        int k = j / 112, mc = j % 112;
        g_Wm2T[j] = Wm2[mc * 256 + k];
    }
}

// ---- one LSTM step: MMA + epilogue (warp-synchronous, acc in regs) ----
// warp = (mg2 = w>>3, r = w&7). m-tiles {mg2, mg2+2}; n-tiles per gate {2r, 2r+1}.
__device__ __forceinline__ void lstm_mma_step(
    char* smem, uint32_t a_addr, uint32_t b_addr,
    int mg2, int r, int lane, float* cst)
{
    float acc[64];   // acc[((mt*4+g)*2+t2)*4 + idx]
#pragma unroll
    for (int i = 0; i < 64; i++) acc[i] = 0.f;

#pragma unroll 3
    for (int ks = 0; ks < KSTEPS; ks++) {
        uint32_t a[2][4];
        ldsm4(a[0][0], a[0][1], a[0][2], a[0][3], a_addr + ks * 32);
        ldsm4(a[1][0], a[1][1], a[1][2], a[1][3], a_addr + 32 * SB + ks * 32);
#pragma unroll
        for (int g = 0; g < 4; g++) {
            uint32_t b0, b1, b2, b3;   // (b0,b1)=tile 2r, (b2,b3)=tile 2r+1
            ldsm4(b0, b1, b2, b3, b_addr + g * GSTRIDE + ks * 32);
#pragma unroll
            for (int mt = 0; mt < 2; mt++) {
                mma4(&acc[((mt * 4 + g) * 2 + 0) * 4], a[mt][0], a[mt][1], a[mt][2], a[mt][3], b0, b1);
                mma4(&acc[((mt * 4 + g) * 2 + 1) * 4], a[mt][0], a[mt][1], a[mt][2], a[mt][3], b2, b3);
            }
        }
    }

    // epilogue: thread-local i/f/g/o per (unit,row); h -> bf16 smem
#pragma unroll
    for (int mt = 0; mt < 2; mt++) {
#pragma unroll
        for (int t2 = 0; t2 < 2; t2++) {
#pragma unroll
            for (int idx = 0; idx < 4; idx++) {
                int rh = idx >> 1, q = idx & 1;
                float pi = acc[((mt * 4 + 0) * 2 + t2) * 4 + idx];
                float pf = acc[((mt * 4 + 1) * 2 + t2) * 4 + idx];
                float pg = acc[((mt * 4 + 2) * 2 + t2) * 4 + idx];
                float po = acc[((mt * 4 + 3) * 2 + t2) * 4 + idx];
                int ci = mt * 8 + t2 * 4 + idx;
                float cn = sigma_(pf) * cst[ci] + sigma_(pi) * tanha_(pg);
                cst[ci] = cn;
                float hn = sigma_(po) * tanha_(cn);
                int row = 16 * mg2 + 32 * mt + (lane >> 2) + 8 * rh;
                if (row < ROWS) {
                    int u = 16 * r + 8 * t2 + 2 * (lane & 3) + q;
                    *(__nv_bfloat16*)(smem + H_OFF + row * SB + u * 2) = __float2bfloat16(hn);
                }
            }
        }
    }
}

// ---- main persistent kernel: 512 threads, 56 rows/CTA ----
__global__ void __launch_bounds__(512, 1)
k_main(const float* __restrict__ obs, const float* __restrict__ bm1,
       const float* __restrict__ bm2, const float* __restrict__ Wr,
       const float* __restrict__ br, const float* __restrict__ z,
       float* __restrict__ out, int B, int T, int S)
{
    extern __shared__ char smem[];
    const int tid = threadIdx.x;
    const int lane = tid & 31, w = tid >> 5;
    const int mg2 = w >> 3, r = w & 7;
    const int b0 = blockIdx.x * ROWS;
    if (T > TMAX) T = TMAX;

    uint32_t sbase = (uint32_t)__cvta_generic_to_shared(smem);
    float* offx_s = (float*)(smem + OFFX_OFF);
    float* offy_s = (float*)(smem + OFFY_OFF);
    float2* base_s = (float2*)(smem + BASE_OFF);
    float* offc = (float*)(smem + OFFC_OFF);
    float* wr_s = (float*)(smem + WRS_OFF);

    // ldmatrix lane address bases
    // A (h rows): m-tile mg2 at rows 16*mg2 (second tile +32 rows handled in-step)
    const uint32_t a_addr = sbase + H_OFF + (16 * mg2 + (lane & 15)) * SB + ((lane >> 4) << 4);
    // B (W gate rows): tiles 2r,2r+1 -> 16 consecutive rows at 16r within each gate block.
    // lanes 0-7: rows 0-7 khalf0; 8-15: rows 0-7 khalf1; 16-23: rows 8-15 khalf0; 24-31: khalf1
    const uint32_t b_addr = sbase + W_OFF + (16 * r + (lane & 7) + ((lane >> 4) << 3)) * SB
                          + (((lane >> 3) & 1) << 4);

    // ---- init: zero h_ext, offsets, Wr, encoder W image ----
    for (int i = tid; i < 4864; i += 512) ((uint32_t*)(smem + H_OFF))[i] = 0;
    if (tid < 256) wr_s[tid] = Wr[tid];
    for (int i = tid; i < ROWS * T; i += 512) {
        int rr = i / T, t = i % T;
        int b = b0 + rr;
        float ox = 0.f, oy = 0.f, cx = 0.f, cy = 0.f;
        if (b < B) {
            cx = obs[((size_t)b * T + t) * 2 + 0];
            cy = obs[((size_t)b * T + t) * 2 + 1];
            float px = 0.f, py = 0.f;
            if (t > 0) {
                px = obs[((size_t)b * T + t - 1) * 2 + 0];
                py = obs[((size_t)b * T + t - 1) * 2 + 1];
            }
            ox = cx - px; oy = cy - py;
        }
        if (t == T - 1) base_s[rr] = make_float2(cx, cy);
        offx_s[t * ROWS + rr] = ox;
        offy_s[t * ROWS + rr] = oy;
    }
    {
        const float4* src = (const float4*)g_wE;
        float4* dst = (float4*)(smem + W_OFF);
        for (int i = tid; i < 9728; i += 512) dst[i] = src[i];
    }
    __syncthreads();
    if (tid < ROWS)   // const-1 column (col 130) for valid rows
        *(__nv_bfloat16*)(smem + H_OFF + tid * SB + 130 * 2) = __float2bfloat16(1.0f);
    // encoder step-0 offsets into h cols 128/129
    if (tid < 112) {
        int rr = tid >> 1, c = tid & 1;
        float v = c ? offy_s[rr] : offx_s[rr];
        *(__nv_bfloat16*)(smem + H_OFF + rr * SB + (128 + c) * 2) = __float2bfloat16(v);
    }

    float cst[16];
#pragma unroll
    for (int i = 0; i < 16; i++) cst[i] = 0.f;

    // ---- encoder ----
    for (int t = 0; t < T; t++) {
        __syncthreads();
        lstm_mma_step(smem, a_addr, b_addr, mg2, r, lane, cst);
        __syncthreads();
        if (t + 1 < T && tid < 112) {
            int rr = tid >> 1, c = tid & 1;
            float v = c ? offy_s[(t + 1) * ROWS + rr] : offx_s[(t + 1) * ROWS + rr];
            *(__nv_bfloat16*)(smem + H_OFF + rr * SB + (128 + c) * 2) = __float2bfloat16(v);
        }
    }
    __syncthreads();

    // ---- MLP (aliases W region: hf [0,28672), m1 [28672,86016)) ----
    {
        float* hf = (float*)(smem + W_OFF);
        float* m1 = (float*)(smem + W_OFF + 28672);
        for (int i = tid; i < ROWS * 128; i += 512) {
            int rr = i >> 7, k = i & 127;
            hf[i] = __bfloat162float(
                *(const __nv_bfloat16*)(smem + H_OFF + rr * SB + k * 2));
        }
        __syncthreads();
        {   // layer 1: m1 = relu(hf @ Wm1^T + bm1)
            int mc = tid & 255, half = tid >> 8;
            for (int rr = half * 28; rr < half * 28 + 28; rr++) {
                float acc = bm1[mc];
                const float* hr = hf + rr * 128;
#pragma unroll 8
                for (int k = 0; k < 128; k++)
                    acc = fmaf(hr[k], g_Wm1T[k * 256 + mc], acc);
                m1[rr * 256 + mc] = fmaxf(acc, 0.f);
            }
        }
        __syncthreads();
        // layer 2 -> h cols 0..111 (bf16), z concat cols 112..127
        if (tid < 448) {
            int n2 = tid % 112, rq = tid / 112;
            for (int rr = rq * 14; rr < rq * 14 + 14; rr++) {
                float acc = bm2[n2];
                const float* mr = m1 + rr * 256;
#pragma unroll 8
                for (int k = 0; k < 256; k++)
                    acc = fmaf(mr[k], g_Wm2T[k * 112 + n2], acc);
                *(__nv_bfloat16*)(smem + H_OFF + rr * SB + n2 * 2) =
                    __float2bfloat16(fmaxf(acc, 0.f));
            }
        }
        for (int i = tid; i < ROWS * 16; i += 512) {
            int rr = i >> 4, zi = i & 15;
            int b = b0 + rr;
            float zv = (b < B) ? z[(size_t)b * 16 + zi] : 0.f;
            *(__nv_bfloat16*)(smem + H_OFF + rr * SB + (112 + zi) * 2) = __float2bfloat16(zv);
        }
        // decoder initial input offsets = last encoder offsets
        if (tid < 112) {
            int rr = tid >> 1, c = tid & 1;
            float v = c ? offy_s[(T - 1) * ROWS + rr] : offx_s[(T - 1) * ROWS + rr];
            if (c == 0) offc[rr] = v; else offc[ROWS + rr] = v;
            *(__nv_bfloat16*)(smem + H_OFF + rr * SB + (128 + c) * 2) = __float2bfloat16(v);
        }
    }
    __syncthreads();
    // decoder W image (overwrites MLP scratch)
    {
        const float4* src = (const float4*)g_wD;
        float4* dst = (float4*)(smem + W_OFF);
        for (int i = tid; i < 9728; i += 512) dst[i] = src[i];
    }
#pragma unroll
    for (int i = 0; i < 16; i++) cst[i] = 0.f;

    // ---- decoder ----
    const int row = tid >> 3;        // 0..63 ; active rows < 56 (tid < 448)
    const int kb = tid & 7;
    const bool ract = (tid < 448);
    float2 mybase = ract ? base_s[row] : make_float2(0.f, 0.f);
    float2 oacc = make_float2(0.f, 0.f);
    float br0 = br[0], br1 = br[1];

    for (int s = 0; s < S; s++) {
        __syncthreads();
        lstm_mma_step(smem, a_addr, b_addr, mg2, r, lane, cst);
        __syncthreads();
        if (ract) {     // readout Wr @ h + br ; cumsum ; stage next offsets
            float p0 = 0.f, p1 = 0.f;
#pragma unroll
            for (int m = 0; m < 16; m++) {
                int k = kb + 8 * m;
                float hv = __bfloat162float(
                    *(const __nv_bfloat16*)(smem + H_OFF + row * SB + k * 2));
                p0 = fmaf(wr_s[k], hv, p0);
                p1 = fmaf(wr_s[128 + k], hv, p1);
            }
            p0 += __shfl_xor_sync(0xffffffffu, p0, 1);
            p0 += __shfl_xor_sync(0xffffffffu, p0, 2);
            p0 += __shfl_xor_sync(0xffffffffu, p0, 4);
            p1 += __shfl_xor_sync(0xffffffffu, p1, 1);
            p1 += __shfl_xor_sync(0xffffffffu, p1, 2);
            p1 += __shfl_xor_sync(0xffffffffu, p1, 4);
            if (kb == 0) {
                float oxv = p0 + br0, oyv = p1 + br1;
                oacc.x += oxv; oacc.y += oyv;
                *(__nv_bfloat16*)(smem + H_OFF + row * SB + 128 * 2) = __float2bfloat16(oxv);
                *(__nv_bfloat16*)(smem + H_OFF + row * SB + 129 * 2) = __float2bfloat16(oyv);
                int b = b0 + row;
                if (b < B) {
                    out[((size_t)b * S + s) * 2 + 0] = mybase.x + oacc.x;
                    out[((size_t)b * S + s) * 2 + 1] = mybase.y + oacc.y;
                }
            }
        }
    }
}

// ---- launch ----
extern "C" void kernel_launch(void* const* d_in, const int* in_sizes, int n_in,
                              void* d_out, int out_size) {
    const float* obs   = (const float*)d_in[0];
    const float* We    = (const float*)d_in[2];
    const float* be    = (const float*)d_in[3];
    const float* Wih_e = (const float*)d_in[4];
    const float* Whh_e = (const float*)d_in[5];
    const float* b_e   = (const float*)d_in[6];
    const float* Wm1   = (const float*)d_in[7];
    const float* bm1   = (const float*)d_in[8];
    const float* Wm2   = (const float*)d_in[9];
    const float* bm2   = (const float*)d_in[10];
    const float* Wd    = (const float*)d_in[11];
    const float* bd    = (const float*)d_in[12];
    const float* Wih_d = (const float*)d_in[13];
    const float* Whh_d = (const float*)d_in[14];
    const float* b_d   = (const float*)d_in[15];
    const float* Wr    = (const float*)d_in[16];
    const float* br    = (const float*)d_in[17];
    const float* z     = (const float*)d_in[18];
    float* out = (float*)d_out;

    int NZ = 16;
    int B = in_sizes[18] / NZ;
    int T = in_sizes[0] / (B * 2);
    int S = out_size / (B * 2);
    int E = in_sizes[2] / 2;

    k_prep<<<256, 256>>>(Wih_e, We, be, b_e, Wih_d, Wd, bd, b_d,
                         Whh_e, Whh_d, Wm1, Wm2, E);

    cudaFuncSetAttribute(k_main, cudaFuncAttributeMaxDynamicSharedMemorySize, SMEM_BYTES);
    int grid = (B + ROWS - 1) / ROWS;
    k_main<<<grid, 512, SMEM_BYTES>>>(obs, bm1, bm2, Wr, br, z, out, B, T, S);
}